// round 8
// baseline (speedup 1.0000x reference)
#include <cuda_runtime.h>
#include <cuda_bf16.h>
#include <cstdint>

#define S_LEN  2048
#define H_DIM  2048
#define V_DIM  32000
#define NSEGC  16
#define R_DIM  256
#define TM_LEN 1024
#define NROWS  6144       /* 4094 main + 2 pad + 2048 math */
#define NSLICE 3
#define NEG_BIG (-1e30f)

/* fp8 quantization scales */
#define SCA    16.0f
#define SCW    64.0f
#define SCINV  (1.0f / (16.0f * 64.0f))

/* CE tiling: CTA 128x256, 512 thr, warps 4m x 4n, warp tile 32x64 */
#define BN     256
#define NPASS  125        /* V / 256 */
#define NKC    16         /* 2048 / 128 per pass */
#define STG    3
#define A_STG  18432      /* 128 rows x 144B */
#define B_STG  36864      /* 256 rows x 144B */
#define SM_LAB 0
#define SM_CMB 512
#define SM_A   7168
#define SM_B   (SM_A + STG * A_STG)
#define SMEM_CE (SM_B + STG * B_STG)     /* 173056 */

/* ------------------------------------------------------------------ */
__device__ uint8_t   g_W8[(size_t)V_DIM * H_DIM];       /* 65.5 MB */
__device__ uint8_t   g_A8[(size_t)NROWS * H_DIM];       /* 12.6 MB */
__device__ float     g_inter[2 * NSEGC * 64 * R_DIM];   /*    2 MB */
__device__ float     g_m [NSLICE * NROWS];
__device__ float     g_l [NSLICE * NROWS];
__device__ float     g_ll[NSLICE * NROWS];
__device__ long long g_off[NROWS];
__device__ int       g_lab[NROWS];
__device__ int       g_flags[NROWS];

/* ------------------------------------------------------------------ */
/* helpers                                                             */
/* ------------------------------------------------------------------ */
__device__ __forceinline__ unsigned long long pack2(float x) {
    unsigned long long r;
    asm("mov.b64 %0, {%1, %1};" : "=l"(r) : "f"(x));
    return r;
}
__device__ __forceinline__ void fma2(unsigned long long& d,
                                     unsigned long long a,
                                     unsigned long long b) {
    asm("fma.rn.f32x2 %0, %1, %2, %0;" : "+l"(d) : "l"(a), "l"(b));
}
__device__ __forceinline__ void unpack2(unsigned long long v, float& lo, float& hi) {
    asm("mov.b64 {%0, %1}, %2;" : "=f"(lo), "=f"(hi) : "l"(v));
}
__device__ __forceinline__ uint16_t f2e4m3x2(float lo, float hi) {
    uint16_t r;
    asm("cvt.rn.satfinite.e4m3x2.f32 %0, %1, %2;" : "=h"(r) : "f"(hi), "f"(lo));
    return r;
}
__device__ __forceinline__ void mma_fp8(float* c, const uint32_t* a,
                                        uint32_t b0, uint32_t b1) {
    asm("mma.sync.aligned.m16n8k32.row.col.f32.e4m3.e4m3.f32 "
        "{%0,%1,%2,%3}, {%4,%5,%6,%7}, {%8,%9}, {%0,%1,%2,%3};"
        : "+f"(c[0]), "+f"(c[1]), "+f"(c[2]), "+f"(c[3])
        : "r"(a[0]), "r"(a[1]), "r"(a[2]), "r"(a[3]), "r"(b0), "r"(b1));
}
#define LDSM_X4(r0, r1, r2, r3, addr) \
    asm volatile("ldmatrix.sync.aligned.m8n8.x4.shared.b16 {%0,%1,%2,%3}, [%4];" \
                 : "=r"(r0), "=r"(r1), "=r"(r2), "=r"(r3) : "r"(addr))

__device__ __forceinline__ uint32_t smem_u32(const void* p) {
    uint32_t a;
    asm("{ .reg .u64 t; cvta.to.shared.u64 t, %1; cvt.u32.u64 %0, t; }"
        : "=r"(a) : "l"(p));
    return a;
}
#define CP_ASYNC16(dst, src) \
    asm volatile("cp.async.cg.shared.global [%0], [%1], 16;" \
                 :: "r"(dst), "l"(src) : "memory")
#define CP_COMMIT() asm volatile("cp.async.commit_group;" ::: "memory")
#define CP_WAIT1()  asm volatile("cp.async.wait_group 1;" ::: "memory")
#define CP_WAIT0()  asm volatile("cp.async.wait_group 0;" ::: "memory")

/* ------------------------------------------------------------------ */
/* setup: row table                                                    */
/* ------------------------------------------------------------------ */
__global__ void setup_kernel(const int* __restrict__ input_ids,
                             const int* __restrict__ attention_mask,
                             const int* __restrict__ starts,
                             const int* __restrict__ ends,
                             const int* __restrict__ math_labels,
                             const int* __restrict__ math_mask) {
    __shared__ int warpsum[8];
    __shared__ int s_rlen[2];
    int tid = threadIdx.x;

    for (int b = 0; b < 2; b++) {
        int v = 0;
        for (int s = tid; s < S_LEN; s += 256) v += attention_mask[b * S_LEN + s];
        #pragma unroll
        for (int m = 16; m; m >>= 1) v += __shfl_xor_sync(0xffffffffu, v, m);
        if ((tid & 31) == 0) warpsum[tid >> 5] = v;
        __syncthreads();
        if (tid == 0) {
            int t = 0;
            for (int w = 0; w < 8; w++) t += warpsum[w];
            s_rlen[b] = t;
        }
        __syncthreads();
    }

    for (int r = tid; r < NROWS; r += 256) {
        long long off; int lab; int fl = 0;
        if (r < 4094) {
            int b = r / 2047;
            int s = r - b * 2047;
            off = (long long)(b * S_LEN + s) * H_DIM;
            lab = input_ids[b * S_LEN + s + 1];
            int st = starts[b], en = ends[b];
            if (s >= st - 1 && s <= en - 1) fl |= 1;
            if (s >= en && s < s_rlen[b] - 1) fl |= 2;
        } else if (r < 4096) {
            off = 0; lab = 0; fl = 0;
        } else {
            int idx = r - 4096;
            int b = idx >> 10, p = idx & 1023;
            off = (long long)(b * TM_LEN + p) * H_DIM;
            lab = math_labels[b * TM_LEN + p];
            fl  = math_mask[b * TM_LEN + p] ? 4 : 0;
        }
        g_off[r] = off; g_lab[r] = lab; g_flags[r] = fl;
    }
}

/* ------------------------------------------------------------------ */
/* convW: W f32 -> e4m3 (x SCW)                                        */
/* ------------------------------------------------------------------ */
__global__ __launch_bounds__(256, 2)
void convW_kernel(const float* __restrict__ W) {
    size_t i = ((size_t)blockIdx.x * 256 + threadIdx.x) * 8;
    float4 x0 = *(const float4*)(W + i);
    float4 x1 = *(const float4*)(W + i + 4);
    uint64_t o =  (uint64_t)f2e4m3x2(x0.x * SCW, x0.y * SCW)
               | ((uint64_t)f2e4m3x2(x0.z * SCW, x0.w * SCW) << 16)
               | ((uint64_t)f2e4m3x2(x1.x * SCW, x1.y * SCW) << 32)
               | ((uint64_t)f2e4m3x2(x1.z * SCW, x1.w * SCW) << 48);
    *(uint64_t*)(g_W8 + i) = o;
}

/* ------------------------------------------------------------------ */
/* convA: gather main rows from hidden -> e4m3 (x SCA), rows 0..4095   */
/* ------------------------------------------------------------------ */
__global__ __launch_bounds__(256, 2)
void convA_kernel(const float* __restrict__ hidden) {
    int row = blockIdx.x;
    const float* src = hidden + g_off[row];
    int k = threadIdx.x * 8;
    float4 x0 = *(const float4*)(src + k);
    float4 x1 = *(const float4*)(src + k + 4);
    uint64_t o =  (uint64_t)f2e4m3x2(x0.x * SCA, x0.y * SCA)
               | ((uint64_t)f2e4m3x2(x0.z * SCA, x0.w * SCA) << 16)
               | ((uint64_t)f2e4m3x2(x1.x * SCA, x1.y * SCA) << 32)
               | ((uint64_t)f2e4m3x2(x1.z * SCA, x1.w * SCA) << 48);
    *(uint64_t*)(g_A8 + (size_t)row * H_DIM + k) = o;
}

/* ------------------------------------------------------------------ */
/* M1: inter = gather(hidden) @ B_seg^T  (K=2048)  grid (32,8)         */
/* CTA: 64 rows x 32 cols                                              */
/* ------------------------------------------------------------------ */
__global__ __launch_bounds__(256, 1)
void m1_kernel(const float* __restrict__ hidden,
               const int*   __restrict__ starts,
               const float* __restrict__ Bm) {
    __shared__ __align__(16) float a_s[64 * 33];
    __shared__ __align__(16) float b_s[32 * 36];
    int tid = threadIdx.x;
    int b   = blockIdx.x >> 4;
    int seg = blockIdx.x & 15;
    int cb  = blockIdx.y;               /* 0..7 : 32-col block of R */
    int st  = starts[b];
    const float* abase = hidden + (long long)(b * S_LEN + st + seg * 64) * H_DIM;
    const float* bbase = Bm + (long long)(seg * R_DIM + cb * 32) * H_DIM;

    int lr = tid >> 2;            /* 0..63 */
    int lk = (tid & 3) * 8;
    int row0 = (tid >> 5) * 8;
    int col  = tid & 31;

    float acc[8];
    #pragma unroll
    for (int i = 0; i < 8; i++) acc[i] = 0.f;

    for (int kt = 0; kt < H_DIM / 32; kt++) {
        int k0 = kt * 32;
        __syncthreads();
        {
            const float* ap = abase + (long long)lr * H_DIM + k0 + lk;
            float4 x0 = *(const float4*)ap;
            float4 x1 = *(const float4*)(ap + 4);
            float* d = a_s + lr * 33 + lk;
            d[0]=x0.x; d[1]=x0.y; d[2]=x0.z; d[3]=x0.w;
            d[4]=x1.x; d[5]=x1.y; d[6]=x1.z; d[7]=x1.w;
            if (tid < 128) {
                int bc = tid >> 2;            /* 0..31 : col */
                int bk = (tid & 3) * 8;
                const float* bp = bbase + (long long)bc * H_DIM + k0 + bk;
                float4 y0 = *(const float4*)bp;
                float4 y1 = *(const float4*)(bp + 4);
                float* e = b_s + bk * 36 + bc;
                e[0*36]=y0.x; e[1*36]=y0.y; e[2*36]=y0.z; e[3*36]=y0.w;
                e[4*36]=y1.x; e[5*36]=y1.y; e[6*36]=y1.z; e[7*36]=y1.w;
            }
        }
        __syncthreads();
        #pragma unroll 8
        for (int kk = 0; kk < 32; kk++) {
            float bv = b_s[kk * 36 + col];
            #pragma unroll
            for (int i = 0; i < 8; i++)
                acc[i] = fmaf(a_s[(row0 + i) * 33 + kk], bv, acc[i]);
        }
    }
    float* out = g_inter + (long long)blockIdx.x * 64 * R_DIM + cb * 32;
    #pragma unroll
    for (int i = 0; i < 8; i++)
        out[(row0 + i) * R_DIM + col] = acc[i];
}

/* ------------------------------------------------------------------ */
/* M2: A rows 4096+ = e4m3((inter @ A_seg^T + bias) x SCA)  (K=256)    */
/* ------------------------------------------------------------------ */
__global__ __launch_bounds__(256, 1)
void m2_kernel(const float* __restrict__ Am,
               const float* __restrict__ bias) {
    __shared__ __align__(16) float a_s[64 * 33];
    __shared__ __align__(16) float b_s[32 * 260];
    int tid = threadIdx.x;
    int bs = blockIdx.x;
    int b = bs >> 4, seg = bs & 15;
    int cb = blockIdx.y;
    const float* abase = g_inter + (long long)bs * 64 * R_DIM;
    const float* bbase = Am + ((long long)seg * H_DIM + cb * 256) * R_DIM;

    int lr = tid >> 2;
    int lk = (tid & 3) * 8;
    int row0 = (tid >> 5) * 8;
    int col0 = (tid & 31) * 8;

    unsigned long long acc[8][4];
    #pragma unroll
    for (int i = 0; i < 8; i++)
        #pragma unroll
        for (int j = 0; j < 4; j++) acc[i][j] = 0ull;

    for (int kt = 0; kt < R_DIM / 32; kt++) {
        int k0 = kt * 32;
        __syncthreads();
        {
            const float* ap = abase + (long long)lr * R_DIM + k0 + lk;
            float4 x0 = *(const float4*)ap;
            float4 x1 = *(const float4*)(ap + 4);
            float* d = a_s + lr * 33 + lk;
            d[0]=x0.x; d[1]=x0.y; d[2]=x0.z; d[3]=x0.w;
            d[4]=x1.x; d[5]=x1.y; d[6]=x1.z; d[7]=x1.w;
            #pragma unroll
            for (int q = 0; q < 4; q++) {
                int col = lr + q * 64;
                const float* bp = bbase + (long long)col * R_DIM + k0 + lk;
                float4 y0 = *(const float4*)bp;
                float4 y1 = *(const float4*)(bp + 4);
                float* e = b_s + lk * 260 + col;
                e[0*260]=y0.x; e[1*260]=y0.y; e[2*260]=y0.z; e[3*260]=y0.w;
                e[4*260]=y1.x; e[5*260]=y1.y; e[6*260]=y1.z; e[7*260]=y1.w;
            }
        }
        __syncthreads();
        #pragma unroll 8
        for (int kk = 0; kk < 32; kk++) {
            float ar[8];
            #pragma unroll
            for (int i = 0; i < 8; i++) ar[i] = a_s[(row0 + i) * 33 + kk];
            ulonglong2 wa = *(const ulonglong2*)(b_s + kk * 260 + col0);
            ulonglong2 wb = *(const ulonglong2*)(b_s + kk * 260 + col0 + 4);
            #pragma unroll
            for (int i = 0; i < 8; i++) {
                unsigned long long h = pack2(ar[i]);
                fma2(acc[i][0], h, wa.x);
                fma2(acc[i][1], h, wa.y);
                fma2(acc[i][2], h, wb.x);
                fma2(acc[i][3], h, wb.y);
            }
        }
    }
    #pragma unroll
    for (int i = 0; i < 8; i++) {
        size_t orow = (size_t)(4096 + b * TM_LEN + seg * 64 + row0 + i) * H_DIM;
        int h0 = cb * 256 + col0;
        float v[8];
        unpack2(acc[i][0], v[0], v[1]);
        unpack2(acc[i][1], v[2], v[3]);
        unpack2(acc[i][2], v[4], v[5]);
        unpack2(acc[i][3], v[6], v[7]);
        #pragma unroll
        for (int j = 0; j < 8; j++)
            v[j] = (v[j] + bias[seg * H_DIM + h0 + j]) * SCA;
        uint64_t o =  (uint64_t)f2e4m3x2(v[0], v[1])
                   | ((uint64_t)f2e4m3x2(v[2], v[3]) << 16)
                   | ((uint64_t)f2e4m3x2(v[4], v[5]) << 32)
                   | ((uint64_t)f2e4m3x2(v[6], v[7]) << 48);
        *(uint64_t*)(g_A8 + orow + h0) = o;
    }
}

/* ------------------------------------------------------------------ */
/* CE: fp8 mma.sync GEMM, 512 thr, continuous cross-pass pipeline      */
/* ------------------------------------------------------------------ */
__global__ __launch_bounds__(512, 1)
void ce_fp8_kernel() {
    extern __shared__ __align__(16) char smem[];
    int*   s_lab = (int*)(smem + SM_LAB);
    float* s_cmb = (float*)(smem + SM_CMB);
    uint32_t sA_u = smem_u32(smem + SM_A);
    uint32_t sB_u = smem_u32(smem + SM_B);

    int tid   = threadIdx.x;
    int rb    = blockIdx.x;
    int slice = blockIdx.y;
    int wid   = tid >> 5, lane = tid & 31;
    int warp_m = wid & 3;           /* 4 warps down M: 32 rows each */
    int warp_n = wid >> 2;          /* 4 warps across N: 64 cols each */
    int g  = lane >> 2;
    int tq = lane & 3;

    if (tid < 128) s_lab[tid] = g_lab[rb * 128 + tid];
    __syncthreads();

    int labr[2][2];
    #pragma unroll
    for (int mt = 0; mt < 2; mt++)
        #pragma unroll
        for (int h = 0; h < 2; h++)
            labr[mt][h] = s_lab[warp_m * 32 + mt * 16 + h * 8 + g];

    /* cp.async loader assignment: A 1024 chunks -> 2/thread, B 2048 -> 4 */
    const uint8_t* Abase = g_A8 + (size_t)(rb * 128) * H_DIM;
    int ar[2], aq[2];
    #pragma unroll
    for (int t = 0; t < 2; t++) {
        int idx = t * 512 + tid;
        ar[t] = idx >> 3; aq[t] = idx & 7;
    }
    int bcol[4], bq[4];
    #pragma unroll
    for (int t = 0; t < 4; t++) {
        int idx = t * 512 + tid;
        bcol[t] = idx >> 3; bq[t] = idx & 7;
    }

    /* ldmatrix per-lane addressing */
    int a_r = lane & 15;
    int a_b = (lane >> 4) * 16;
    int b_c = (lane & 7) + ((lane >> 4) & 1) * 8;
    int b_b = ((lane >> 3) & 1) * 16;

    int p0 = (slice * NPASS) / NSLICE;
    int p1 = ((slice + 1) * NPASS) / NSLICE;
    int nch = (p1 - p0) * NKC;

    float m_run[2][2], l_run[2][2], ll[2][2];
    #pragma unroll
    for (int mt = 0; mt < 2; mt++)
        #pragma unroll
        for (int h = 0; h < 2; h++) {
            m_run[mt][h] = NEG_BIG; l_run[mt][h] = 0.f; ll[mt][h] = NEG_BIG;
        }

    float acc[2][8][4];
    #pragma unroll
    for (int mt = 0; mt < 2; mt++)
        #pragma unroll
        for (int nt = 0; nt < 8; nt++)
            #pragma unroll
            for (int j = 0; j < 4; j++) acc[mt][nt][j] = 0.f;

    auto load_stage = [&](int ci) {
        int s = ci % STG;
        int pass = p0 + (ci >> 4);
        int kc = ci & 15;
        uint32_t da = sA_u + (uint32_t)s * A_STG;
        uint32_t db = sB_u + (uint32_t)s * B_STG;
        int kb = kc * 128;
        const uint8_t* Bb = g_W8 + (size_t)(pass * BN) * H_DIM;
        #pragma unroll
        for (int t = 0; t < 2; t++) {
            const void* src = (const void*)(Abase + (size_t)ar[t] * H_DIM + kb + aq[t] * 16);
            CP_ASYNC16(da + (uint32_t)(ar[t] * 144 + aq[t] * 16), src);
        }
        #pragma unroll
        for (int t = 0; t < 4; t++) {
            const void* src = (const void*)(Bb + (size_t)bcol[t] * H_DIM + kb + bq[t] * 16);
            CP_ASYNC16(db + (uint32_t)(bcol[t] * 144 + bq[t] * 16), src);
        }
        CP_COMMIT();
    };

    load_stage(0);
    if (nch > 1) load_stage(1);

    for (int ci = 0; ci < nch; ci++) {
        if (ci + 1 < nch) CP_WAIT1(); else CP_WAIT0();
        __syncthreads();
        if (ci + 2 < nch) load_stage(ci + 2);

        int s = ci % STG;
        uint32_t aAddr = sA_u + (uint32_t)s * A_STG
                       + (uint32_t)((warp_m * 32 + a_r) * 144 + a_b);
        uint32_t bAddr = sB_u + (uint32_t)s * B_STG
                       + (uint32_t)((warp_n * 64 + b_c) * 144 + b_b);

        #pragma unroll
        for (int ks = 0; ks < 4; ks++) {
            int ko = ks * 32;
            uint32_t af[2][4];
            #pragma unroll
            for (int mt = 0; mt < 2; mt++)
                LDSM_X4(af[mt][0], af[mt][1], af[mt][2], af[mt][3],
                        aAddr + mt * 16 * 144 + ko);
            #pragma unroll
            for (int p = 0; p < 4; p++) {
                uint32_t r0, r1, r2, r3;
                LDSM_X4(r0, r1, r2, r3, bAddr + p * 16 * 144 + ko);
                #pragma unroll
                for (int mt = 0; mt < 2; mt++) {
                    mma_fp8(acc[mt][2 * p],     af[mt], r0, r1);
                    mma_fp8(acc[mt][2 * p + 1], af[mt], r2, r3);
                }
            }
        }

        if ((ci & 15) == 15) {
            /* pass complete: online logsumexp over this 256-col pass */
            int vbase = (p0 + (ci >> 4)) * BN;
            #pragma unroll
            for (int mt = 0; mt < 2; mt++) {
                #pragma unroll
                for (int h = 0; h < 2; h++) {
                    float cm = NEG_BIG;
                    #pragma unroll
                    for (int nt = 0; nt < 8; nt++) {
                        cm = fmaxf(cm, acc[mt][nt][2 * h]);
                        cm = fmaxf(cm, acc[mt][nt][2 * h + 1]);
                    }
                    cm *= SCINV;
                    cm = fmaxf(cm, __shfl_xor_sync(0xffffffffu, cm, 1));
                    cm = fmaxf(cm, __shfl_xor_sync(0xffffffffu, cm, 2));
                    float mn = fmaxf(m_run[mt][h], cm);
                    float ssum = 0.f;
                    int cbase = vbase + warp_n * 64 + 2 * tq;
                    int lb = labr[mt][h];
                    #pragma unroll
                    for (int nt = 0; nt < 8; nt++) {
                        float v0 = acc[mt][nt][2 * h]     * SCINV;
                        float v1 = acc[mt][nt][2 * h + 1] * SCINV;
                        ssum += __expf(v0 - mn) + __expf(v1 - mn);
                        int cc = cbase + nt * 8;
                        if (cc == lb)     ll[mt][h] = v0;
                        if (cc + 1 == lb) ll[mt][h] = v1;
                        acc[mt][nt][2 * h] = 0.f;
                        acc[mt][nt][2 * h + 1] = 0.f;
                    }
                    ssum += __shfl_xor_sync(0xffffffffu, ssum, 1);
                    ssum += __shfl_xor_sync(0xffffffffu, ssum, 2);
                    l_run[mt][h] = l_run[mt][h] * __expf(m_run[mt][h] - mn) + ssum;
                    m_run[mt][h] = mn;
                }
            }
        }
    }

    /* combine 4 n-warps via smem, write per-slice partials */
    #pragma unroll
    for (int mt = 0; mt < 2; mt++) {
        #pragma unroll
        for (int h = 0; h < 2; h++) {
            float lv = ll[mt][h];
            lv = fmaxf(lv, __shfl_xor_sync(0xffffffffu, lv, 1));
            lv = fmaxf(lv, __shfl_xor_sync(0xffffffffu, lv, 2));
            if (tq == 0) {
                int row = warp_m * 32 + mt * 16 + h * 8 + g;
                s_cmb[(warp_n * 3 + 0) * 128 + row] = m_run[mt][h];
                s_cmb[(warp_n * 3 + 1) * 128 + row] = l_run[mt][h];
                s_cmb[(warp_n * 3 + 2) * 128 + row] = lv;
            }
        }
    }
    __syncthreads();
    if (tid < 128) {
        int row = tid;
        float m = NEG_BIG, llv = NEG_BIG;
        #pragma unroll
        for (int j = 0; j < 4; j++) {
            m   = fmaxf(m,   s_cmb[(j * 3 + 0) * 128 + row]);
            llv = fmaxf(llv, s_cmb[(j * 3 + 2) * 128 + row]);
        }
        float l = 0.f;
        #pragma unroll
        for (int j = 0; j < 4; j++)
            l += s_cmb[(j * 3 + 1) * 128 + row]
               * __expf(s_cmb[(j * 3 + 0) * 128 + row] - m);
        int grow = rb * 128 + row;
        g_m [slice * NROWS + grow] = m;
        g_l [slice * NROWS + grow] = l;
        g_ll[slice * NROWS + grow] = llv;
    }
}

/* ------------------------------------------------------------------ */
/* final: merge slices -> nll -> masked means -> 4 outputs             */
/* ------------------------------------------------------------------ */
__global__ void reduce_kernel(float* __restrict__ out, int out_size) {
    __shared__ float sred[6][8];
    int tid = threadIdx.x;
    float vals[6] = {0.f, 0.f, 0.f, 0.f, 0.f, 0.f};

    for (int r = tid; r < NROWS; r += 256) {
        int fl = g_flags[r];
        if (!fl) continue;
        float m0 = g_m[r], m1 = g_m[NROWS + r], m2 = g_m[2 * NROWS + r];
        float m = fmaxf(m0, fmaxf(m1, m2));
        float l = g_l[r] * __expf(m0 - m)
                + g_l[NROWS + r] * __expf(m1 - m)
                + g_l[2 * NROWS + r] * __expf(m2 - m);
        float llv = fmaxf(g_ll[r], fmaxf(g_ll[NROWS + r], g_ll[2 * NROWS + r]));
        float nll = m + logf(l) - llv;
        if (fl & 4) { vals[0] += nll; vals[1] += 1.f; }
        if (fl & 1) { vals[2] += nll; vals[3] += 1.f; }
        if (fl & 2) { vals[4] += nll; vals[5] += 1.f; }
    }
    #pragma unroll
    for (int k = 0; k < 6; k++) {
        float v = vals[k];
        #pragma unroll
        for (int m = 16; m; m >>= 1) v += __shfl_xor_sync(0xffffffffu, v, m);
        if ((tid & 31) == 0) sred[k][tid >> 5] = v;
    }
    __syncthreads();
    if (tid == 0) {
        float tot[6];
        #pragma unroll
        for (int k = 0; k < 6; k++) {
            float a = 0.f;
            for (int w = 0; w < 8; w++) a += sred[k][w];
            tot[k] = a;
        }
        float math_loss = tot[0] / fmaxf(tot[1], 1.f);
        float st_loss   = tot[2] / fmaxf(tot[3], 1.f);
        float fa_loss   = tot[4] / fmaxf(tot[5], 1.f);
        float total = 0.5f * math_loss + 0.5f * st_loss + 0.4f * fa_loss;
        if (out_size > 0) out[0] = total;
        if (out_size > 1) out[1] = math_loss;
        if (out_size > 2) out[2] = st_loss;
        if (out_size > 3) out[3] = fa_loss;
        for (int i = 4; i < out_size; i++) out[i] = 0.f;
    }
}

/* ------------------------------------------------------------------ */
extern "C" void kernel_launch(void* const* d_in, const int* in_sizes, int n_in,
                              void* d_out, int out_size) {
    const float* hidden   = (const float*)d_in[0];
    const int*   ids      = (const int*)d_in[1];
    const int*   amask    = (const int*)d_in[2];
    const int*   starts   = (const int*)d_in[3];
    const int*   ends     = (const int*)d_in[4];
    const int*   mlab     = (const int*)d_in[5];
    const int*   mmask    = (const int*)d_in[6];
    const float* Amat     = (const float*)d_in[8];
    const float* Bmat     = (const float*)d_in[9];
    const float* bias     = (const float*)d_in[10];
    const float* W        = (const float*)d_in[11];
    float* out = (float*)d_out;

    static int smem_set = 0;
    if (!smem_set) {
        cudaFuncSetAttribute(ce_fp8_kernel,
                             cudaFuncAttributeMaxDynamicSharedMemorySize, SMEM_CE);
        smem_set = 1;
    }

    setup_kernel<<<1, 256>>>(ids, amask, starts, ends, mlab, mmask);
    convW_kernel<<<V_DIM * H_DIM / 2048, 256>>>(W);
    convA_kernel<<<4096, 256>>>(hidden);
    m1_kernel<<<dim3(32, 8), 256>>>(hidden, starts, Bmat);
    m2_kernel<<<dim3(32, 8), 256>>>(Amat, bias);
    ce_fp8_kernel<<<dim3(48, NSLICE), 512, SMEM_CE>>>();
    reduce_kernel<<<1, 256>>>(out, out_size);
}